// round 6
// baseline (speedup 1.0000x reference)
#include <cuda_runtime.h>
#include <cstdint>

// x:               [256, 30, 30, 512] f32   = [230400 pixels][128 float4]
// pattern_indices: [230400]           int32 (harness downcasts int64)
// spatial_pe:      [900][64]          float4
// pattern_pe:      [64][64]           float4
// out = x + concat(spatial_pe[hw], pattern_pe[idx & 63]) per pixel
//
// R3 geometry (proven best): blockDim=128, 4 consecutive pixels per block,
// thread t owns channel-float4 d4 = t. Warp-uniform branch, MLP=4 front-batch.
// This round's single delta: __stwt write-through stores (last untried
// streaming-write policy) to probe the DRAM R/W-mix ceiling.

#define HW        900
#define PIX_TOTAL (256 * 900)       // 230400
#define PIX_PER_BLOCK 4

__global__ void __launch_bounds__(128)
pe_add_kernel(const float4* __restrict__ x,
              const int*    __restrict__ pattern_indices,
              const float4* __restrict__ spatial_pe,   // [900*64]
              const float4* __restrict__ pattern_pe,   // [64*64]
              float4*       __restrict__ out)
{
    const int t    = threadIdx.x;             // 0..127 == d4
    const int pix0 = blockIdx.x * PIX_PER_BLOCK;
    const int base = pix0 * 128 + t;          // < 29.5M, fits int32

    const bool is_pattern = (t >= 64);

    // Start the dependent gather chain early: pattern-index loads first.
    int idx[PIX_PER_BLOCK];
    if (is_pattern) {
#pragma unroll
        for (int k = 0; k < PIX_PER_BLOCK; k++)
            idx[k] = __ldg(&pattern_indices[pix0 + k]);
    }

    // Front-batch the 4 streaming x loads (independent, warp-coalesced 512B).
    float4 xv[PIX_PER_BLOCK];
#pragma unroll
    for (int k = 0; k < PIX_PER_BLOCK; k++)
        xv[k] = __ldcs(&x[base + k * 128]);

    float4 pe[PIX_PER_BLOCK];
    if (!is_pattern) {
        // spatial half: hw = pixel % 900, consecutive pixels -> hw0+k with wrap
        int hw0 = pix0 % HW;
#pragma unroll
        for (int k = 0; k < PIX_PER_BLOCK; k++) {
            int hw = hw0 + k;
            if (hw >= HW) hw -= HW;
            pe[k] = __ldg(&spatial_pe[hw * 64 + t]);
        }
    } else {
#pragma unroll
        for (int k = 0; k < PIX_PER_BLOCK; k++)
            pe[k] = __ldg(&pattern_pe[(idx[k] & 63) * 64 + (t - 64)]);
    }

#pragma unroll
    for (int k = 0; k < PIX_PER_BLOCK; k++) {
        xv[k].x += pe[k].x;
        xv[k].y += pe[k].y;
        xv[k].z += pe[k].z;
        xv[k].w += pe[k].w;
        __stwt(&out[base + k * 128], xv[k]);   // write-through, no L2 allocate
    }
}

extern "C" void kernel_launch(void* const* d_in, const int* in_sizes, int n_in,
                              void* d_out, int out_size)
{
    const float4* x   = (const float4*)d_in[0];
    const int*    pid = (const int*)d_in[1];
    const float4* spe = (const float4*)d_in[2];
    const float4* ppe = (const float4*)d_in[3];
    float4*       out = (float4*)d_out;

    const int grid = PIX_TOTAL / PIX_PER_BLOCK;   // 57600 blocks
    pe_add_kernel<<<grid, 128>>>(x, pid, spe, ppe, out);
}

// round 7
// speedup vs baseline: 1.0097x; 1.0097x over previous
#include <cuda_runtime.h>
#include <cstdint>

// x:               [256, 30, 30, 512] f32   = [230400 pixels][128 float4]
// pattern_indices: [230400]           int32 (harness downcasts int64)
// spatial_pe:      [900][64]          float4
// pattern_pe:      [64][64]           float4
// out = x + concat(spatial_pe[hw], pattern_pe[idx & 63]) per pixel
//
// FINAL (R3 geometry, best measured 137.7us end-to-end / 131.7us kernel):
//   blockDim=128, 4 consecutive pixels per block, thread t owns channel d4=t.
//   - warp-uniform spatial/pattern branch (t<64 vs t>=64)
//   - 4 independent front-batched x loads (MLP=4) -> DRAM latency hidden
//   - single %900 per thread, wrap by conditional subtract
//   - plain loads/stores: cache-hint probes (R5 __ldcs/__stcs, R6 __stwt)
//     were neutral-to-negative; kernel sits at the mixed-R/W HBM ceiling
//     (~6.8 TB/s, 85% of spec) with issue=12%, alu=6% -> memory-floor bound.

#define HW        900
#define PIX_TOTAL (256 * 900)       // 230400
#define PIX_PER_BLOCK 4

__global__ void __launch_bounds__(128)
pe_add_kernel(const float4* __restrict__ x,
              const int*    __restrict__ pattern_indices,
              const float4* __restrict__ spatial_pe,   // [900*64]
              const float4* __restrict__ pattern_pe,   // [64*64]
              float4*       __restrict__ out)
{
    const int t    = threadIdx.x;             // 0..127 == d4
    const int pix0 = blockIdx.x * PIX_PER_BLOCK;
    const int base = pix0 * 128 + t;          // < 29.5M, fits int32

    // Front-batch the 4 streaming x loads (independent, warp-coalesced 512B).
    float4 xv[PIX_PER_BLOCK];
#pragma unroll
    for (int k = 0; k < PIX_PER_BLOCK; k++)
        xv[k] = x[base + k * 128];

    float4 pe[PIX_PER_BLOCK];
    if (t < 64) {
        // spatial half: hw = pixel % 900, consecutive pixels -> hw0+k with wrap
        int hw0 = pix0 % HW;
#pragma unroll
        for (int k = 0; k < PIX_PER_BLOCK; k++) {
            int hw = hw0 + k;
            if (hw >= HW) hw -= HW;
            pe[k] = spatial_pe[hw * 64 + t];
        }
    } else {
        // pattern half: per-pixel gather (index load broadcasts across the warp)
        int idx[PIX_PER_BLOCK];
#pragma unroll
        for (int k = 0; k < PIX_PER_BLOCK; k++)
            idx[k] = pattern_indices[pix0 + k] & 63;
#pragma unroll
        for (int k = 0; k < PIX_PER_BLOCK; k++)
            pe[k] = pattern_pe[idx[k] * 64 + (t - 64)];
    }

#pragma unroll
    for (int k = 0; k < PIX_PER_BLOCK; k++) {
        xv[k].x += pe[k].x;
        xv[k].y += pe[k].y;
        xv[k].z += pe[k].z;
        xv[k].w += pe[k].w;
        out[base + k * 128] = xv[k];
    }
}

extern "C" void kernel_launch(void* const* d_in, const int* in_sizes, int n_in,
                              void* d_out, int out_size)
{
    const float4* x   = (const float4*)d_in[0];
    const int*    pid = (const int*)d_in[1];
    const float4* spe = (const float4*)d_in[2];
    const float4* ppe = (const float4*)d_in[3];
    float4*       out = (float4*)d_out;

    const int grid = PIX_TOTAL / PIX_PER_BLOCK;   // 57600 blocks
    pe_add_kernel<<<grid, 128>>>(x, pid, spe, ppe, out);
}

// round 8
// speedup vs baseline: 1.0114x; 1.0016x over previous
#include <cuda_runtime.h>
#include <cstdint>

// x:               [256, 30, 30, 512] f32   = [230400 pixels][512 floats]
// pattern_indices: [230400]           int32 (harness downcasts int64)
// spatial_pe:      [900][256]         f32
// pattern_pe:      [64][256]          f32
// out = x + concat(spatial_pe[hw], pattern_pe[idx & 63]) per pixel
//
// R8 probe: 256-bit global accesses (sm_100+ ld/st.global.v8.b32).
// blockDim=128 = 2 pixel-lanes (sub) x 64 chunk-lanes (c); chunk = 8 floats.
//   - warp 0 of each pair: c=0..31  -> spatial half  (channels 0..255)
//   - warp 1 of each pair: c=32..63 -> pattern half  (channels 256..511)
//   branch stays warp-uniform.
// Each pixel-lane handles 4 pixels (p, p+2, p+4, p+6) -> 8 pixels/block,
// 4 front-batched independent 32B loads per thread (MLP=4, proven sufficient).

#define HW        900
#define PIX_TOTAL (256 * 900)       // 230400
#define PIX_PER_BLOCK 8

__device__ __forceinline__ void ldg_v8(const float* p, uint32_t* v) {
    asm volatile("ld.global.v8.b32 {%0,%1,%2,%3,%4,%5,%6,%7}, [%8];"
        : "=r"(v[0]), "=r"(v[1]), "=r"(v[2]), "=r"(v[3]),
          "=r"(v[4]), "=r"(v[5]), "=r"(v[6]), "=r"(v[7])
        : "l"(p));
}

__device__ __forceinline__ void stg_v8(float* p, const uint32_t* v) {
    asm volatile("st.global.v8.b32 [%0], {%1,%2,%3,%4,%5,%6,%7,%8};"
        :: "l"(p),
           "r"(v[0]), "r"(v[1]), "r"(v[2]), "r"(v[3]),
           "r"(v[4]), "r"(v[5]), "r"(v[6]), "r"(v[7])
        : "memory");
}

__global__ void __launch_bounds__(128)
pe_add_kernel(const float* __restrict__ x,
              const int*   __restrict__ pattern_indices,
              const float* __restrict__ spatial_pe,   // [900*256]
              const float* __restrict__ pattern_pe,   // [64*256]
              float*       __restrict__ out)
{
    const int t    = threadIdx.x;
    const int sub  = t >> 6;          // 0..1  pixel-lane
    const int c    = t & 63;          // 0..63 chunk-lane (8 floats each)
    const int pix0 = blockIdx.x * PIX_PER_BLOCK + sub;   // this lane's first pixel

    // This thread's 4 pixels: pix0, pix0+2, pix0+4, pix0+6
    // x offset for pixel p, chunk c: p*512 + c*8 floats

    uint32_t xv[4][8];
#pragma unroll
    for (int k = 0; k < 4; k++) {
        int p = pix0 + 2 * k;
        ldg_v8(x + (int64_t)p * 512 + c * 8, xv[k]);
    }

    uint32_t pe[4][8];
    if (c < 32) {
        // spatial half: hw = pixel % 900; pixels step by 2, wrap by subtract
        int hw0 = pix0 % HW;
#pragma unroll
        for (int k = 0; k < 4; k++) {
            int hw = hw0 + 2 * k;
            if (hw >= HW) hw -= HW;
            ldg_v8(spatial_pe + hw * 256 + c * 8, pe[k]);
        }
    } else {
        int cc = c - 32;
#pragma unroll
        for (int k = 0; k < 4; k++) {
            int idx = pattern_indices[pix0 + 2 * k] & 63;
            ldg_v8(pattern_pe + idx * 256 + cc * 8, pe[k]);
        }
    }

#pragma unroll
    for (int k = 0; k < 4; k++) {
#pragma unroll
        for (int j = 0; j < 8; j++) {
            float s = __uint_as_float(xv[k][j]) + __uint_as_float(pe[k][j]);
            xv[k][j] = __float_as_uint(s);
        }
        int p = pix0 + 2 * k;
        stg_v8(out + (int64_t)p * 512 + c * 8, xv[k]);
    }
}

extern "C" void kernel_launch(void* const* d_in, const int* in_sizes, int n_in,
                              void* d_out, int out_size)
{
    const float* x   = (const float*)d_in[0];
    const int*   pid = (const int*)d_in[1];
    const float* spe = (const float*)d_in[2];
    const float* ppe = (const float*)d_in[3];
    float*       out = (float*)d_out;

    const int grid = PIX_TOTAL / PIX_PER_BLOCK;   // 28800 blocks
    pe_add_kernel<<<grid, 128>>>(x, pid, spe, ppe, out);
}